// round 5
// baseline (speedup 1.0000x reference)
#include <cuda_runtime.h>
#include <cuda_bf16.h>
#include <cstdint>

// SVD_Solver: batched weighted Kabsch via Horn quaternion method.
// points (B,M,3) f32, weight (B,M,J) f32, offset (B,M,J,3) f32.
// out = [R (B,J,3,3) ; t (B,J,3)], f32.
//
// R5: cp.async double-buffered pipeline. Each block handles NB=4 batches;
// batch i+1's full 25KB is prefetched (cp.async.cg, 16B) while batch i is
// reduced+solved. Conflict-free smem reduction + warp-0 de-duped solve.

#define B_N 4096
#define M_N 64
#define J_N 24
#define NB  4                       // batches per block
#define GRID (B_N / NB)             // 1024

#define O_FLOATS (M_N * J_N * 3)    // 4608
#define W_FLOATS (M_N * J_N)        // 1536
#define Q_FLOATS (M_N * 3)          // 192
#define BUF_FLOATS (O_FLOATS + W_FLOATS + Q_FLOATS)   // 6336 (25344 B)
#define SUM_STRIDE 23               // 22 sums + pad, gcd(23,32)=1

__device__ __forceinline__ void cp_async16(uint32_t smem_addr, const void* gptr) {
    asm volatile("cp.async.cg.shared.global [%0], [%1], 16;\n"
                 :: "r"(smem_addr), "l"(gptr));
}
__device__ __forceinline__ void cp_commit() {
    asm volatile("cp.async.commit_group;\n");
}
template <int N>
__device__ __forceinline__ void cp_wait() {
    asm volatile("cp.async.wait_group %0;\n" :: "n"(N));
}

__global__ void __launch_bounds__(128)
svd_solver_kernel(const float* __restrict__ points,
                  const float* __restrict__ weight,
                  const float* __restrict__ offset,
                  float* __restrict__ out)
{
    extern __shared__ __align__(16) float dsm[];        // 2 * BUF_FLOATS
    __shared__ float sums[J_N * SUM_STRIDE];

    const int tid = threadIdx.x;
    const int b0 = blockIdx.x * NB;

    // Issue async stage of batch (b0 + i) into buffer buf (0/1).
    auto stage = [&](int i, int buf) {
        float* d = dsm + buf * BUF_FLOATS;
        uint32_t dbase = (uint32_t)__cvta_generic_to_shared(d);
        const float* go = offset + (size_t)(b0 + i) * O_FLOATS;
        const float* gw = weight + (size_t)(b0 + i) * W_FLOATS;
        const float* gq = points + (size_t)(b0 + i) * Q_FLOATS;
#pragma unroll
        for (int k = 0; k < O_FLOATS / 4; k += 128)      // 9 iters
            cp_async16(dbase + (k + tid) * 16, go + (k + tid) * 4);
#pragma unroll
        for (int k = 0; k < W_FLOATS / 4; k += 128)      // 3 iters
            cp_async16(dbase + (O_FLOATS + (k + tid) * 4) * 4, gw + (k + tid) * 4);
        if (tid < Q_FLOATS / 4)
            cp_async16(dbase + (O_FLOATS + W_FLOATS + tid * 4) * 4, gq + tid * 4);
        cp_commit();
    };

    stage(0, 0);

#pragma unroll 1
    for (int i = 0; i < NB; ++i) {
        if (i + 1 < NB) {
            stage(i + 1, (i + 1) & 1);
            cp_wait<1>();            // batch i's buffer complete
        } else {
            cp_wait<0>();
        }
        __syncthreads();

        const float* buf = dsm + (i & 1) * BUF_FLOATS;
        const float* smo = buf;
        const float* smw = buf + O_FLOATS;
        const float* smq = buf + O_FLOATS + W_FLOATS;

        // ---- Reduction: 96 threads = 24 j * 4 sub; mm = 4*ml + sub ----
        if (tid < 96) {
            const int j = tid >> 2;
            const int sub = tid & 3;

            float sw = 0.f;
            float sP0 = 0.f, sP1 = 0.f, sP2 = 0.f;
            float sQ0 = 0.f, sQ1 = 0.f, sQ2 = 0.f;
            float wP0 = 0.f, wP1 = 0.f, wP2 = 0.f;
            float wQ0 = 0.f, wQ1 = 0.f, wQ2 = 0.f;
            float s00 = 0.f, s01 = 0.f, s02 = 0.f;
            float s10 = 0.f, s11 = 0.f, s12 = 0.f;
            float s20 = 0.f, s21 = 0.f, s22 = 0.f;

#pragma unroll
            for (int ml = 0; ml < M_N / 4; ++ml) {
                const int mm = ml * 4 + sub;
                float w  = smw[mm * J_N + j];
                const float* po = smo + (mm * J_N + j) * 3;
                float p0 = po[0], p1 = po[1], p2 = po[2];
                const float* pq = smq + mm * 3;
                float q0 = pq[0], q1 = pq[1], q2 = pq[2];

                sw += w;
                sP0 += p0; sP1 += p1; sP2 += p2;
                sQ0 += q0; sQ1 += q1; sQ2 += q2;
                wP0 = fmaf(w, p0, wP0); wP1 = fmaf(w, p1, wP1); wP2 = fmaf(w, p2, wP2);
                wQ0 = fmaf(w, q0, wQ0); wQ1 = fmaf(w, q1, wQ1); wQ2 = fmaf(w, q2, wQ2);
                s00 = fmaf(p0, q0, s00); s01 = fmaf(p0, q1, s01); s02 = fmaf(p0, q2, s02);
                s10 = fmaf(p1, q0, s10); s11 = fmaf(p1, q1, s11); s12 = fmaf(p1, q2, s12);
                s20 = fmaf(p2, q0, s20); s21 = fmaf(p2, q1, s21); s22 = fmaf(p2, q2, s22);
            }

#pragma unroll
            for (int d = 1; d < 4; d <<= 1) {
                sw  += __shfl_xor_sync(0xffffffffu, sw,  d);
                sP0 += __shfl_xor_sync(0xffffffffu, sP0, d);
                sP1 += __shfl_xor_sync(0xffffffffu, sP1, d);
                sP2 += __shfl_xor_sync(0xffffffffu, sP2, d);
                sQ0 += __shfl_xor_sync(0xffffffffu, sQ0, d);
                sQ1 += __shfl_xor_sync(0xffffffffu, sQ1, d);
                sQ2 += __shfl_xor_sync(0xffffffffu, sQ2, d);
                wP0 += __shfl_xor_sync(0xffffffffu, wP0, d);
                wP1 += __shfl_xor_sync(0xffffffffu, wP1, d);
                wP2 += __shfl_xor_sync(0xffffffffu, wP2, d);
                wQ0 += __shfl_xor_sync(0xffffffffu, wQ0, d);
                wQ1 += __shfl_xor_sync(0xffffffffu, wQ1, d);
                wQ2 += __shfl_xor_sync(0xffffffffu, wQ2, d);
                s00 += __shfl_xor_sync(0xffffffffu, s00, d);
                s01 += __shfl_xor_sync(0xffffffffu, s01, d);
                s02 += __shfl_xor_sync(0xffffffffu, s02, d);
                s10 += __shfl_xor_sync(0xffffffffu, s10, d);
                s11 += __shfl_xor_sync(0xffffffffu, s11, d);
                s12 += __shfl_xor_sync(0xffffffffu, s12, d);
                s20 += __shfl_xor_sync(0xffffffffu, s20, d);
                s21 += __shfl_xor_sync(0xffffffffu, s21, d);
                s22 += __shfl_xor_sync(0xffffffffu, s22, d);
            }

            if (sub == 0) {
                float* s = sums + j * SUM_STRIDE;
                s[0]  = sw;
                s[1]  = sP0; s[2]  = sP1; s[3]  = sP2;
                s[4]  = sQ0; s[5]  = sQ1; s[6]  = sQ2;
                s[7]  = wP0; s[8]  = wP1; s[9]  = wP2;
                s[10] = wQ0; s[11] = wQ1; s[12] = wQ2;
                s[13] = s00; s[14] = s01; s[15] = s02;
                s[16] = s10; s[17] = s11; s[18] = s12;
                s[19] = s20; s[20] = s21; s[21] = s22;
            }
        }
        __syncthreads();

        // ---- Solve: warp 0, one j per lane ----
        if (tid < J_N) {
            const float* s = sums + tid * SUM_STRIDE;
            float Tsw = s[0];
            float TsP0 = s[1],  TsP1 = s[2],  TsP2 = s[3];
            float TsQ0 = s[4],  TsQ1 = s[5],  TsQ2 = s[6];
            float TwP0 = s[7],  TwP1 = s[8],  TwP2 = s[9];
            float TwQ0 = s[10], TwQ1 = s[11], TwQ2 = s[12];
            float t00 = s[13], t01 = s[14], t02 = s[15];
            float t10 = s[16], t11 = s[17], t12 = s[18];
            float t20 = s[19], t21 = s[20], t22 = s[21];

            float inv = 1.0f / Tsw;
            float Pb0 = TwP0 * inv, Pb1 = TwP1 * inv, Pb2 = TwP2 * inv;
            float Qb0 = TwQ0 * inv, Qb1 = TwQ1 * inv, Qb2 = TwQ2 * inv;

            float g0 = TsP0 - (float)M_N * Pb0;
            float g1 = TsP1 - (float)M_N * Pb1;
            float g2 = TsP2 - (float)M_N * Pb2;

            float Sxx = t00 - Pb0 * TsQ0 - g0 * Qb0;
            float Sxy = t01 - Pb0 * TsQ1 - g0 * Qb1;
            float Sxz = t02 - Pb0 * TsQ2 - g0 * Qb2;
            float Syx = t10 - Pb1 * TsQ0 - g1 * Qb0;
            float Syy = t11 - Pb1 * TsQ1 - g1 * Qb1;
            float Syz = t12 - Pb1 * TsQ2 - g1 * Qb2;
            float Szx = t20 - Pb2 * TsQ0 - g2 * Qb0;
            float Szy = t21 - Pb2 * TsQ1 - g2 * Qb1;
            float Szz = t22 - Pb2 * TsQ2 - g2 * Qb2;

            float n00 = Sxx + Syy + Szz;
            float n01 = Syz - Szy;
            float n02 = Szx - Sxz;
            float n03 = Sxy - Syx;
            float n11 = Sxx - Syy - Szz;
            float n12 = Sxy + Syx;
            float n13 = Szx + Sxz;
            float n22 = -Sxx + Syy - Szz;
            float n23 = Syz + Szy;
            float n33 = -Sxx - Syy + Szz;

            float f2 = n00 * n00 + n11 * n11 + n22 * n22 + n33 * n33 +
                       2.0f * (n01 * n01 + n02 * n02 + n03 * n03 +
                               n12 * n12 + n13 * n13 + n23 * n23);
            float sh = sqrtf(f2) + 1e-30f;

            float b00 = n00 + sh, b01 = n01, b02 = n02, b03 = n03;
            float b11 = n11 + sh, b12 = n12, b13 = n13;
            float b22 = n22 + sh, b23 = n23;
            float b33 = n33 + sh;

#pragma unroll 1
            for (int it = 0; it < 16; ++it) {
                float c00 = b00 * b00 + b01 * b01 + b02 * b02 + b03 * b03;
                float c01 = b00 * b01 + b01 * b11 + b02 * b12 + b03 * b13;
                float c02 = b00 * b02 + b01 * b12 + b02 * b22 + b03 * b23;
                float c03 = b00 * b03 + b01 * b13 + b02 * b23 + b03 * b33;
                float c11 = b01 * b01 + b11 * b11 + b12 * b12 + b13 * b13;
                float c12 = b01 * b02 + b11 * b12 + b12 * b22 + b13 * b23;
                float c13 = b01 * b03 + b11 * b13 + b12 * b23 + b13 * b33;
                float c22 = b02 * b02 + b12 * b12 + b22 * b22 + b23 * b23;
                float c23 = b02 * b03 + b12 * b13 + b22 * b23 + b23 * b33;
                float c33 = b03 * b03 + b13 * b13 + b23 * b23 + b33 * b33;
                float tr = c00 + c11 + c22 + c33;
                float sc = __frcp_rn(tr);
                b00 = c00 * sc; b01 = c01 * sc; b02 = c02 * sc; b03 = c03 * sc;
                b11 = c11 * sc; b12 = c12 * sc; b13 = c13 * sc;
                b22 = c22 * sc; b23 = c23 * sc;
                b33 = c33 * sc;
            }

            float q0, q1, q2, q3;
            if (b00 >= b11 && b00 >= b22 && b00 >= b33) {
                q0 = b00; q1 = b01; q2 = b02; q3 = b03;
            } else if (b11 >= b22 && b11 >= b33) {
                q0 = b01; q1 = b11; q2 = b12; q3 = b13;
            } else if (b22 >= b33) {
                q0 = b02; q1 = b12; q2 = b22; q3 = b23;
            } else {
                q0 = b03; q1 = b13; q2 = b23; q3 = b33;
            }
            float nq = rsqrtf(q0 * q0 + q1 * q1 + q2 * q2 + q3 * q3);
            q0 *= nq; q1 *= nq; q2 *= nq; q3 *= nq;

            float xx = q1 * q1, yy = q2 * q2, zz = q3 * q3;
            float xy = q1 * q2, xz = q1 * q3, yz = q2 * q3;
            float wx = q0 * q1, wy = q0 * q2, wz = q0 * q3;

            float R00 = 1.0f - 2.0f * (yy + zz);
            float R01 = 2.0f * (xy - wz);
            float R02 = 2.0f * (xz + wy);
            float R10 = 2.0f * (xy + wz);
            float R11 = 1.0f - 2.0f * (xx + zz);
            float R12 = 2.0f * (yz - wx);
            float R20 = 2.0f * (xz - wy);
            float R21 = 2.0f * (yz + wx);
            float R22 = 1.0f - 2.0f * (xx + yy);

            float tx = Qb0 - (R00 * Pb0 + R01 * Pb1 + R02 * Pb2);
            float ty = Qb1 - (R10 * Pb0 + R11 * Pb1 + R12 * Pb2);
            float tz = Qb2 - (R20 * Pb0 + R21 * Pb1 + R22 * Pb2);

            const int grp_out = (b0 + i) * J_N + tid;
            float* oR = out + (size_t)grp_out * 9;
            oR[0] = R00; oR[1] = R01; oR[2] = R02;
            oR[3] = R10; oR[4] = R11; oR[5] = R12;
            oR[6] = R20; oR[7] = R21; oR[8] = R22;

            float* oT = out + (size_t)B_N * J_N * 9 + (size_t)grp_out * 3;
            oT[0] = tx; oT[1] = ty; oT[2] = tz;
        }
        __syncthreads();   // sums + buffer (i&1) free for reuse next round
    }
}

extern "C" void kernel_launch(void* const* d_in, const int* in_sizes, int n_in,
                              void* d_out, int out_size)
{
    const float* points = (const float*)d_in[0];
    const float* weight = (const float*)d_in[1];
    const float* offset = (const float*)d_in[2];
    float* out = (float*)d_out;

    const int smem_bytes = 2 * BUF_FLOATS * sizeof(float);   // 50688
    cudaFuncSetAttribute(svd_solver_kernel,
                         cudaFuncAttributeMaxDynamicSharedMemorySize, smem_bytes);
    svd_solver_kernel<<<GRID, 128, smem_bytes>>>(points, weight, offset, out);
}

// round 7
// speedup vs baseline: 1.2000x; 1.2000x over previous
#include <cuda_runtime.h>
#include <cuda_bf16.h>
#include <cstdint>

// SVD_Solver: batched weighted Kabsch via Horn quaternion method.
// points (B,M,3) f32, weight (B,M,J) f32, offset (B,M,J,3) f32.
// out = [R (B,J,3,3) ; t (B,J,3)], f32.
//
// R7 (= R6 with fixed cp.async addressing): occupancy-first. One block per
// batch; offset staged in two 9KB cp.async halves (both issued up-front,
// compute of half0 overlaps arrival of half1); weight read directly from
// global inside the compute loop. ~21.4KB smem -> 10 CTAs/SM.

#define B_N 4096
#define M_N 64
#define J_N 24

#define O_HALF (32 * J_N * 3)       // 2304 floats = 9216 B per half
#define Q_FLOATS (M_N * 3)          // 192
#define SUM_STRIDE 23               // 22 sums + pad, gcd(23,32)=1

__device__ __forceinline__ void cp_async16(uint32_t smem_addr, const void* gptr) {
    asm volatile("cp.async.cg.shared.global [%0], [%1], 16;\n"
                 :: "r"(smem_addr), "l"(gptr));
}
__device__ __forceinline__ void cp_commit() {
    asm volatile("cp.async.commit_group;\n");
}
template <int N>
__device__ __forceinline__ void cp_wait() {
    asm volatile("cp.async.wait_group %0;\n" :: "n"(N));
}

__global__ void __launch_bounds__(128)
svd_solver_kernel(const float* __restrict__ points,
                  const float* __restrict__ weight,
                  const float* __restrict__ offset,
                  float* __restrict__ out)
{
    __shared__ __align__(16) float smo[2 * O_HALF];    // two offset halves
    __shared__ __align__(16) float smq[Q_FLOATS];
    __shared__ float sums[J_N * SUM_STRIDE];

    const int tid = threadIdx.x;
    const int b = blockIdx.x;

    const float* go = offset + (size_t)b * (M_N * J_N * 3);
    const float* gw = weight + (size_t)b * (M_N * J_N);
    const float* gq = points + (size_t)b * Q_FLOATS;

    // ---- Stage: group A = {offset half0, points}, group B = {offset half1} ----
    {
        const uint32_t so = (uint32_t)__cvta_generic_to_shared(smo);
        const uint32_t sq = (uint32_t)__cvta_generic_to_shared(smq);
#pragma unroll
        for (int k = 0; k < 5; ++k) {                  // 576 float4s / 128 thr
            int idx = k * 128 + tid;
            if (idx < O_HALF / 4)
                cp_async16(so + idx * 16, go + idx * 4);
        }
        if (tid < Q_FLOATS / 4)
            cp_async16(sq + tid * 16, gq + tid * 4);
        cp_commit();                                   // group A
#pragma unroll
        for (int k = 0; k < 5; ++k) {
            int idx = k * 128 + tid;
            if (idx < O_HALF / 4)
                cp_async16(so + O_HALF * 4 + idx * 16, go + O_HALF + idx * 4);
        }
        cp_commit();                                   // group B
    }

    const int j = tid >> 2;          // 0..23 (valid when tid < 96)
    const int sub = tid & 3;

    float sw = 0.f;
    float sP0 = 0.f, sP1 = 0.f, sP2 = 0.f;
    float sQ0 = 0.f, sQ1 = 0.f, sQ2 = 0.f;
    float wP0 = 0.f, wP1 = 0.f, wP2 = 0.f;
    float wQ0 = 0.f, wQ1 = 0.f, wQ2 = 0.f;
    float s00 = 0.f, s01 = 0.f, s02 = 0.f;
    float s10 = 0.f, s11 = 0.f, s12 = 0.f;
    float s20 = 0.f, s21 = 0.f, s22 = 0.f;

#pragma unroll 1
    for (int half = 0; half < 2; ++half) {
        if (half == 0) cp_wait<1>(); else cp_wait<0>();
        __syncthreads();

        if (tid < 96) {
            const int mbase = half * 32;
            const float* ob = smo + half * O_HALF;

            // Hoisted global weight loads for this half (8 in flight).
            float wreg[8];
#pragma unroll
            for (int ml = 0; ml < 8; ++ml)
                wreg[ml] = gw[(mbase + ml * 4 + sub) * J_N + j];

#pragma unroll
            for (int ml = 0; ml < 8; ++ml) {
                const int m_local = ml * 4 + sub;
                const float* po = ob + (m_local * J_N + j) * 3;
                float p0 = po[0], p1 = po[1], p2 = po[2];
                const float* pq = smq + (mbase + m_local) * 3;
                float q0 = pq[0], q1 = pq[1], q2 = pq[2];
                float w = wreg[ml];

                sw += w;
                sP0 += p0; sP1 += p1; sP2 += p2;
                sQ0 += q0; sQ1 += q1; sQ2 += q2;
                wP0 = fmaf(w, p0, wP0); wP1 = fmaf(w, p1, wP1); wP2 = fmaf(w, p2, wP2);
                wQ0 = fmaf(w, q0, wQ0); wQ1 = fmaf(w, q1, wQ1); wQ2 = fmaf(w, q2, wQ2);
                s00 = fmaf(p0, q0, s00); s01 = fmaf(p0, q1, s01); s02 = fmaf(p0, q2, s02);
                s10 = fmaf(p1, q0, s10); s11 = fmaf(p1, q1, s11); s12 = fmaf(p1, q2, s12);
                s20 = fmaf(p2, q0, s20); s21 = fmaf(p2, q1, s21); s22 = fmaf(p2, q2, s22);
            }
        }
    }

    if (tid < 96) {
        // Butterfly across the 4 adjacent-lane sub partners.
#pragma unroll
        for (int d = 1; d < 4; d <<= 1) {
            sw  += __shfl_xor_sync(0xffffffffu, sw,  d);
            sP0 += __shfl_xor_sync(0xffffffffu, sP0, d);
            sP1 += __shfl_xor_sync(0xffffffffu, sP1, d);
            sP2 += __shfl_xor_sync(0xffffffffu, sP2, d);
            sQ0 += __shfl_xor_sync(0xffffffffu, sQ0, d);
            sQ1 += __shfl_xor_sync(0xffffffffu, sQ1, d);
            sQ2 += __shfl_xor_sync(0xffffffffu, sQ2, d);
            wP0 += __shfl_xor_sync(0xffffffffu, wP0, d);
            wP1 += __shfl_xor_sync(0xffffffffu, wP1, d);
            wP2 += __shfl_xor_sync(0xffffffffu, wP2, d);
            wQ0 += __shfl_xor_sync(0xffffffffu, wQ0, d);
            wQ1 += __shfl_xor_sync(0xffffffffu, wQ1, d);
            wQ2 += __shfl_xor_sync(0xffffffffu, wQ2, d);
            s00 += __shfl_xor_sync(0xffffffffu, s00, d);
            s01 += __shfl_xor_sync(0xffffffffu, s01, d);
            s02 += __shfl_xor_sync(0xffffffffu, s02, d);
            s10 += __shfl_xor_sync(0xffffffffu, s10, d);
            s11 += __shfl_xor_sync(0xffffffffu, s11, d);
            s12 += __shfl_xor_sync(0xffffffffu, s12, d);
            s20 += __shfl_xor_sync(0xffffffffu, s20, d);
            s21 += __shfl_xor_sync(0xffffffffu, s21, d);
            s22 += __shfl_xor_sync(0xffffffffu, s22, d);
        }
        if (sub == 0) {
            float* s = sums + j * SUM_STRIDE;
            s[0]  = sw;
            s[1]  = sP0; s[2]  = sP1; s[3]  = sP2;
            s[4]  = sQ0; s[5]  = sQ1; s[6]  = sQ2;
            s[7]  = wP0; s[8]  = wP1; s[9]  = wP2;
            s[10] = wQ0; s[11] = wQ1; s[12] = wQ2;
            s[13] = s00; s[14] = s01; s[15] = s02;
            s[16] = s10; s[17] = s11; s[18] = s12;
            s[19] = s20; s[20] = s21; s[21] = s22;
        }
    }
    __syncthreads();

    if (tid >= J_N) return;

    // ---- Solve: warp 0, one j per lane ----
    const float* s = sums + tid * SUM_STRIDE;
    float Tsw = s[0];
    float TsP0 = s[1],  TsP1 = s[2],  TsP2 = s[3];
    float TsQ0 = s[4],  TsQ1 = s[5],  TsQ2 = s[6];
    float TwP0 = s[7],  TwP1 = s[8],  TwP2 = s[9];
    float TwQ0 = s[10], TwQ1 = s[11], TwQ2 = s[12];
    float t00 = s[13], t01 = s[14], t02 = s[15];
    float t10 = s[16], t11 = s[17], t12 = s[18];
    float t20 = s[19], t21 = s[20], t22 = s[21];

    float inv = 1.0f / Tsw;
    float Pb0 = TwP0 * inv, Pb1 = TwP1 * inv, Pb2 = TwP2 * inv;
    float Qb0 = TwQ0 * inv, Qb1 = TwQ1 * inv, Qb2 = TwQ2 * inv;

    float g0 = TsP0 - (float)M_N * Pb0;
    float g1 = TsP1 - (float)M_N * Pb1;
    float g2 = TsP2 - (float)M_N * Pb2;

    float Sxx = t00 - Pb0 * TsQ0 - g0 * Qb0;
    float Sxy = t01 - Pb0 * TsQ1 - g0 * Qb1;
    float Sxz = t02 - Pb0 * TsQ2 - g0 * Qb2;
    float Syx = t10 - Pb1 * TsQ0 - g1 * Qb0;
    float Syy = t11 - Pb1 * TsQ1 - g1 * Qb1;
    float Syz = t12 - Pb1 * TsQ2 - g1 * Qb2;
    float Szx = t20 - Pb2 * TsQ0 - g2 * Qb0;
    float Szy = t21 - Pb2 * TsQ1 - g2 * Qb1;
    float Szz = t22 - Pb2 * TsQ2 - g2 * Qb2;

    float n00 = Sxx + Syy + Szz;
    float n01 = Syz - Szy;
    float n02 = Szx - Sxz;
    float n03 = Sxy - Syx;
    float n11 = Sxx - Syy - Szz;
    float n12 = Sxy + Syx;
    float n13 = Szx + Sxz;
    float n22 = -Sxx + Syy - Szz;
    float n23 = Syz + Szy;
    float n33 = -Sxx - Syy + Szz;

    float f2 = n00 * n00 + n11 * n11 + n22 * n22 + n33 * n33 +
               2.0f * (n01 * n01 + n02 * n02 + n03 * n03 +
                       n12 * n12 + n13 * n13 + n23 * n23);
    float sh = sqrtf(f2) + 1e-30f;

    float b00 = n00 + sh, b01 = n01, b02 = n02, b03 = n03;
    float b11 = n11 + sh, b12 = n12, b13 = n13;
    float b22 = n22 + sh, b23 = n23;
    float b33 = n33 + sh;

#pragma unroll 1
    for (int it = 0; it < 16; ++it) {
        float c00 = b00 * b00 + b01 * b01 + b02 * b02 + b03 * b03;
        float c01 = b00 * b01 + b01 * b11 + b02 * b12 + b03 * b13;
        float c02 = b00 * b02 + b01 * b12 + b02 * b22 + b03 * b23;
        float c03 = b00 * b03 + b01 * b13 + b02 * b23 + b03 * b33;
        float c11 = b01 * b01 + b11 * b11 + b12 * b12 + b13 * b13;
        float c12 = b01 * b02 + b11 * b12 + b12 * b22 + b13 * b23;
        float c13 = b01 * b03 + b11 * b13 + b12 * b23 + b13 * b33;
        float c22 = b02 * b02 + b12 * b12 + b22 * b22 + b23 * b23;
        float c23 = b02 * b03 + b12 * b13 + b22 * b23 + b23 * b33;
        float c33 = b03 * b03 + b13 * b13 + b23 * b23 + b33 * b33;
        float tr = c00 + c11 + c22 + c33;
        float sc = __frcp_rn(tr);
        b00 = c00 * sc; b01 = c01 * sc; b02 = c02 * sc; b03 = c03 * sc;
        b11 = c11 * sc; b12 = c12 * sc; b13 = c13 * sc;
        b22 = c22 * sc; b23 = c23 * sc;
        b33 = c33 * sc;
    }

    float q0, q1, q2, q3;
    if (b00 >= b11 && b00 >= b22 && b00 >= b33) {
        q0 = b00; q1 = b01; q2 = b02; q3 = b03;
    } else if (b11 >= b22 && b11 >= b33) {
        q0 = b01; q1 = b11; q2 = b12; q3 = b13;
    } else if (b22 >= b33) {
        q0 = b02; q1 = b12; q2 = b22; q3 = b23;
    } else {
        q0 = b03; q1 = b13; q2 = b23; q3 = b33;
    }
    float nq = rsqrtf(q0 * q0 + q1 * q1 + q2 * q2 + q3 * q3);
    q0 *= nq; q1 *= nq; q2 *= nq; q3 *= nq;

    float xx = q1 * q1, yy = q2 * q2, zz = q3 * q3;
    float xy = q1 * q2, xz = q1 * q3, yz = q2 * q3;
    float wx = q0 * q1, wy = q0 * q2, wz = q0 * q3;

    float R00 = 1.0f - 2.0f * (yy + zz);
    float R01 = 2.0f * (xy - wz);
    float R02 = 2.0f * (xz + wy);
    float R10 = 2.0f * (xy + wz);
    float R11 = 1.0f - 2.0f * (xx + zz);
    float R12 = 2.0f * (yz - wx);
    float R20 = 2.0f * (xz - wy);
    float R21 = 2.0f * (yz + wx);
    float R22 = 1.0f - 2.0f * (xx + yy);

    float tx = Qb0 - (R00 * Pb0 + R01 * Pb1 + R02 * Pb2);
    float ty = Qb1 - (R10 * Pb0 + R11 * Pb1 + R12 * Pb2);
    float tz = Qb2 - (R20 * Pb0 + R21 * Pb1 + R22 * Pb2);

    const int grp_out = b * J_N + tid;
    float* oR = out + (size_t)grp_out * 9;
    oR[0] = R00; oR[1] = R01; oR[2] = R02;
    oR[3] = R10; oR[4] = R11; oR[5] = R12;
    oR[6] = R20; oR[7] = R21; oR[8] = R22;

    float* oT = out + (size_t)B_N * J_N * 9 + (size_t)grp_out * 3;
    oT[0] = tx; oT[1] = ty; oT[2] = tz;
}

extern "C" void kernel_launch(void* const* d_in, const int* in_sizes, int n_in,
                              void* d_out, int out_size)
{
    const float* points = (const float*)d_in[0];
    const float* weight = (const float*)d_in[1];
    const float* offset = (const float*)d_in[2];
    float* out = (float*)d_out;

    svd_solver_kernel<<<B_N, 128>>>(points, weight, offset, out);
}